// round 2
// baseline (speedup 1.0000x reference)
#include <cuda_runtime.h>

#define NB      10     // basis functions per dim
#define DEG     3
#define KN      14     // knots per dim
#define ROWS    256    // rows per block
#define THREADS 256
#define NCOEF   33     // (12 + 11 + 10) recurrence steps per dim

__global__ __launch_bounds__(THREADS)
void bspline_outer_kernel(const float* __restrict__ t,
                          const float* __restrict__ knots,
                          float* __restrict__ out,
                          int B)
{
    __shared__ float  skn[2][KN];
    __shared__ float4 scoef[2][NCOEF];      // (inv1, -kn[i]*inv1, -inv2, kn[i+k+1]*inv2)
    __shared__ float  B0s[ROWS][NB + 1];    // pad to 11: conflict-free phase-1 writes
    __shared__ float  B1s[ROWS][NB + 1];

    const int tid = threadIdx.x;

    // ---- load knots ----
    if (tid < 2 * KN)
        skn[tid / KN][tid % KN] = knots[tid];
    __syncthreads();

    // ---- precompute Cox-de Boor reciprocal coefficients (no per-row divides) ----
    if (tid < 2 * NCOEF) {
        int d = tid / NCOEF;
        int r = tid % NCOEF;
        int k, i;
        if      (r < 12) { k = 1; i = r; }
        else if (r < 23) { k = 2; i = r - 12; }
        else             { k = 3; i = r - 23; }
        const float* kd = skn[d];
        float d1 = kd[i + k]     - kd[i];
        float d2 = kd[i + k + 1] - kd[i + 1];
        float inv1 = (d1 == 0.0f) ? 0.0f : 1.0f / d1;
        float inv2 = (d2 == 0.0f) ? 0.0f : 1.0f / d2;
        // w1 = (t - kn[i]) / d1      = fma(t,  inv1, -kn[i]*inv1)
        // w2 = (kn[i+k+1] - t) / d2  = fma(t, -inv2,  kn[i+k+1]*inv2)
        scoef[d][r] = make_float4(inv1, -kd[i] * inv1, -inv2, kd[i + k + 1] * inv2);
    }
    __syncthreads();

    const long long row0 = (long long)blockIdx.x * ROWS;
    const int grow = (int)row0 + tid;

    // ---- phase 1: each thread computes both 10-wide bases for its row ----
    if (grow < B) {
        float2 tv = ((const float2*)t)[grow];
        float tt[2] = { tv.x, tv.y };
        #pragma unroll
        for (int d = 0; d < 2; d++) {
            const float tc = tt[d];
            const float* kd = skn[d];
            float Bv[13];
            #pragma unroll
            for (int i = 0; i < 13; i++)
                Bv[i] = (kd[i] <= tc && tc < kd[i + 1]) ? 1.0f : 0.0f;

            int r = 0;
            #pragma unroll
            for (int k = 1; k <= DEG; k++) {
                #pragma unroll
                for (int i = 0; i < 13 - k; i++) {
                    float4 cc = scoef[d][r]; r++;
                    float w1 = fmaf(tc, cc.x, cc.y);
                    float w2 = fmaf(tc, cc.z, cc.w);
                    Bv[i] = w1 * Bv[i] + w2 * Bv[i + 1];
                }
            }
            if (d == 0) {
                #pragma unroll
                for (int i = 0; i < NB; i++) B0s[tid][i] = Bv[i];
            } else {
                #pragma unroll
                for (int i = 0; i < NB; i++) B1s[tid][i] = Bv[i];
            }
        }
    }
    __syncthreads();

    // ---- phase 2: cooperative coalesced float4 stores of the 256x100 tile ----
    // Each thread owns float4 indices q, q+256, q+512, ... within the tile.
    // 25 float4s per row; row/rem tracked incrementally (no divide in loop body).
    const int vr = (int)min((long long)ROWS, (long long)B - row0);  // valid rows
    const int vq = vr * 25;                                          // float4s in tile
    float4* out4 = (float4*)out + row0 * 25;

    int row = tid / 25;
    int rem = tid - row * 25;
    for (int q = tid; q < vq; q += THREADS) {
        int c0 = rem * 4;           // starting column (0..96), stays inside the row
        int i  = c0 / 10;
        int j  = c0 - i * 10;
        float4 v;
        v.x = B0s[row][i] * B1s[row][j]; if (++j == 10) { j = 0; ++i; }
        v.y = B0s[row][i] * B1s[row][j]; if (++j == 10) { j = 0; ++i; }
        v.z = B0s[row][i] * B1s[row][j]; if (++j == 10) { j = 0; ++i; }
        v.w = B0s[row][i] * B1s[row][j];
        out4[q] = v;
        // advance by THREADS=256 float4s: +10 rows, +6 rem (256 = 10*25 + 6)
        row += 10;
        rem += 6;
        if (rem >= 25) { rem -= 25; row += 1; }
    }
}

extern "C" void kernel_launch(void* const* d_in, const int* in_sizes, int n_in,
                              void* d_out, int out_size)
{
    const float* t     = (const float*)d_in[0];
    const float* knots = (const float*)d_in[1];
    float* out         = (float*)d_out;
    int B = in_sizes[0] / 2;                     // t is (B, 2)
    int grid = (B + ROWS - 1) / ROWS;
    bspline_outer_kernel<<<grid, THREADS>>>(t, knots, out, B);
}

// round 4
// speedup vs baseline: 1.0351x; 1.0351x over previous
#include <cuda_runtime.h>

#define NB      10     // basis functions per dim
#define DEG     3
#define KN      14     // knots per dim
#define ROWS    256    // rows per block
#define THREADS 256
#define NCOEF   33     // (12 + 11 + 10) recurrence steps per dim

__global__ __launch_bounds__(THREADS)
void bspline_outer_kernel(const float* __restrict__ t,
                          const float* __restrict__ knots,
                          float* __restrict__ out,
                          int B)
{
    __shared__ float  skn[2][KN];
    __shared__ float4 scoef[2][NCOEF];      // (inv1, -kn[i]*inv1, -inv2, kn[i+k+1]*inv2)
    __shared__ float  B0s[ROWS][NB + 1];    // stride 11: conflict-free phase-1 writes
    __shared__ float  B1s[ROWS][NB + 1];

    const int tid = threadIdx.x;

    // ---- load knots ----
    if (tid < 2 * KN)
        skn[tid / KN][tid % KN] = knots[tid];
    __syncthreads();

    // ---- precompute Cox-de Boor reciprocal coefficients (no per-row divides) ----
    if (tid < 2 * NCOEF) {
        int d = tid / NCOEF;
        int r = tid % NCOEF;
        int k, i;
        if      (r < 12) { k = 1; i = r; }
        else if (r < 23) { k = 2; i = r - 12; }
        else             { k = 3; i = r - 23; }
        const float* kd = skn[d];
        float d1 = kd[i + k]     - kd[i];
        float d2 = kd[i + k + 1] - kd[i + 1];
        float inv1 = (d1 == 0.0f) ? 0.0f : 1.0f / d1;
        float inv2 = (d2 == 0.0f) ? 0.0f : 1.0f / d2;
        // w1 = (t - kn[i]) / d1      = fma(t,  inv1, -kn[i]*inv1)
        // w2 = (kn[i+k+1] - t) / d2  = fma(t, -inv2,  kn[i+k+1]*inv2)
        scoef[d][r] = make_float4(inv1, -kd[i] * inv1, -inv2, kd[i + k + 1] * inv2);
    }
    __syncthreads();

    const long long row0 = (long long)blockIdx.x * ROWS;
    const int grow = (int)row0 + tid;

    // ---- phase 1: each thread computes both 10-wide bases for its row ----
    if (grow < B) {
        float2 tv = ((const float2*)t)[grow];
        float tt[2] = { tv.x, tv.y };
        #pragma unroll
        for (int d = 0; d < 2; d++) {
            const float tc = tt[d];
            const float* kd = skn[d];
            float Bv[13];
            #pragma unroll
            for (int i = 0; i < 13; i++)
                Bv[i] = (kd[i] <= tc && tc < kd[i + 1]) ? 1.0f : 0.0f;

            int r = 0;
            #pragma unroll
            for (int k = 1; k <= DEG; k++) {
                #pragma unroll
                for (int i = 0; i < 13 - k; i++) {
                    float4 cc = scoef[d][r]; r++;
                    float w1 = fmaf(tc, cc.x, cc.y);
                    float w2 = fmaf(tc, cc.z, cc.w);
                    Bv[i] = w1 * Bv[i] + w2 * Bv[i + 1];
                }
            }
            if (d == 0) {
                #pragma unroll
                for (int i = 0; i < NB; i++) B0s[tid][i] = Bv[i];
            } else {
                #pragma unroll
                for (int i = 0; i < NB; i++) B1s[tid][i] = Bv[i];
            }
        }
    }
    __syncthreads();

    // ---- phase 2: warp-per-row, lane-constant element mapping ----
    // Warp w handles rows w, w+8, w+16, ... ; lane l (<25) owns float4 #l of
    // each row.  (i,j) indices are lane constants hoisted out of the loop, so
    // the body is 6 broadcast-LDS + 4 FMUL + 1 STG.128 + 1 IADD.
    const int lane = tid & 31;
    const int warp = tid >> 5;

    if (lane >= 25) return;           // no barriers after this point

    const int c0 = lane * 4;          // starting column 0..96 (within one row)
    int ei0, ej0, ei1, ej1, ei2, ej2, ei3, ej3;
    {
        int i = c0 / 10, j = c0 - (c0 / 10) * 10;
        ei0 = i; ej0 = j; if (++j == 10) { j = 0; ++i; }
        ei1 = i; ej1 = j; if (++j == 10) { j = 0; ++i; }
        ei2 = i; ej2 = j; if (++j == 10) { j = 0; ++i; }
        ei3 = i; ej3 = j;
    }

    const int vr = (int)min((long long)ROWS, (long long)B - row0);  // valid rows
    float4* out4 = (float4*)out + row0 * 25;

    for (int r = warp; r < vr; r += 8) {
        float4 v;
        v.x = B0s[r][ei0] * B1s[r][ej0];
        v.y = B0s[r][ei1] * B1s[r][ej1];
        v.z = B0s[r][ei2] * B1s[r][ej2];
        v.w = B0s[r][ei3] * B1s[r][ej3];
        out4[r * 25 + lane] = v;
    }
}

extern "C" void kernel_launch(void* const* d_in, const int* in_sizes, int n_in,
                              void* d_out, int out_size)
{
    const float* t     = (const float*)d_in[0];
    const float* knots = (const float*)d_in[1];
    float* out         = (float*)d_out;
    int B = in_sizes[0] / 2;                     // t is (B, 2)
    int grid = (B + ROWS - 1) / ROWS;
    bspline_outer_kernel<<<grid, THREADS>>>(t, knots, out, B);
}

// round 5
// speedup vs baseline: 1.0428x; 1.0074x over previous
#include <cuda_runtime.h>

#define NB      10     // basis functions per dim
#define DEG     3
#define KN      14     // knots per dim
#define ROWS    256    // rows per block
#define THREADS 256
#define NCOEF   33     // (12 + 11 + 10) recurrence steps per dim

__global__ __launch_bounds__(THREADS)
void bspline_outer_kernel(const float* __restrict__ t,
                          const float* __restrict__ knots,
                          float* __restrict__ out,
                          int B)
{
    __shared__ float  skn[2][KN];
    __shared__ float4 scoef[2][NCOEF];   // (inv1, -kn[i]*inv1, -inv2, kn[i+k+1]*inv2)
    __shared__ float  B0s[ROWS][NB + 1]; // stride 11: conflict-free scalar access
    __shared__ float2 B1es[ROWS][7];     // wrap-extended B1, float2 pairs, stride 14 words

    const int tid = threadIdx.x;

    // ---- load knots ----
    if (tid < 2 * KN)
        skn[tid / KN][tid % KN] = knots[tid];
    __syncthreads();

    // ---- precompute Cox-de Boor reciprocal coefficients (no per-row divides) ----
    if (tid < 2 * NCOEF) {
        int d = tid / NCOEF;
        int r = tid % NCOEF;
        int k, i;
        if      (r < 12) { k = 1; i = r; }
        else if (r < 23) { k = 2; i = r - 12; }
        else             { k = 3; i = r - 23; }
        const float* kd = skn[d];
        float d1 = kd[i + k]     - kd[i];
        float d2 = kd[i + k + 1] - kd[i + 1];
        float inv1 = (d1 == 0.0f) ? 0.0f : 1.0f / d1;
        float inv2 = (d2 == 0.0f) ? 0.0f : 1.0f / d2;
        scoef[d][r] = make_float4(inv1, -kd[i] * inv1, -inv2, kd[i + k + 1] * inv2);
    }
    __syncthreads();

    const long long row0 = (long long)blockIdx.x * ROWS;
    const int grow = (int)row0 + tid;

    // ---- phase 1: each thread computes both 10-wide bases for its row ----
    if (grow < B) {
        float2 tv = ((const float2*)t)[grow];
        float tt[2] = { tv.x, tv.y };
        #pragma unroll
        for (int d = 0; d < 2; d++) {
            const float tc = tt[d];
            const float* kd = skn[d];
            float Bv[13];
            #pragma unroll
            for (int i = 0; i < 13; i++)
                Bv[i] = (kd[i] <= tc && tc < kd[i + 1]) ? 1.0f : 0.0f;

            int r = 0;
            #pragma unroll
            for (int k = 1; k <= DEG; k++) {
                #pragma unroll
                for (int i = 0; i < 13 - k; i++) {
                    float4 cc = scoef[d][r]; r++;
                    float w1 = fmaf(tc, cc.x, cc.y);
                    float w2 = fmaf(tc, cc.z, cc.w);
                    Bv[i] = w1 * Bv[i] + w2 * Bv[i + 1];
                }
            }
            if (d == 0) {
                #pragma unroll
                for (int i = 0; i < NB; i++) B0s[tid][i] = Bv[i];
            } else {
                // wrap-extended B1 as float2 pairs: indices 0..11 cover j0..j0+3
                // for every even j0 in {0..8}
                #pragma unroll
                for (int p = 0; p < 5; p++)
                    B1es[tid][p] = make_float2(Bv[2 * p], Bv[2 * p + 1]);
                B1es[tid][5] = make_float2(Bv[0], Bv[1]);  // wrap: indices 10,11
            }
        }
    }
    __syncthreads();

    // ---- phase 2: warp-per-row, lane-constant mapping, vector B1 fetch ----
    // Lane l (<25) owns columns c0..c0+3, c0 = 4l. j0 = c0 mod 10 is even, so
    // the four B1 values are two aligned float2s of the wrap-extended row.
    // B0 needs at most 2 distinct values (i0, i3); SELs pick per element.
    const int lane = tid & 31;
    const int warp = tid >> 5;

    if (lane >= 25) return;           // no barriers after this point

    const int c0 = lane * 4;
    const int i0 = c0 / 10;
    const int j0 = c0 - 10 * i0;      // even
    const int hp = j0 >> 1;           // float2 pair index
    const int i1 = (c0 + 1) / 10;
    const int i2 = (c0 + 2) / 10;
    const int i3 = (c0 + 3) / 10;
    const bool s1 = (i1 == i0);       // lane constants
    const bool s2 = (i2 == i0);

    float4* out4 = (float4*)out + row0 * 25;

    if (row0 + ROWS <= (long long)B) {
        // full tile: compile-time trip count, unrolled for MLP
        #pragma unroll 4
        for (int r = warp; r < ROWS; r += 8) {
            float2 pA = B1es[r][hp];
            float2 pB = B1es[r][hp + 1];
            float  a  = B0s[r][i0];
            float  dd = B0s[r][i3];
            float  m1 = s1 ? a : dd;
            float  m2 = s2 ? a : dd;
            float4 v;
            v.x = a  * pA.x;
            v.y = m1 * pA.y;
            v.z = m2 * pB.x;
            v.w = dd * pB.y;
            out4[r * 25 + lane] = v;
        }
    } else {
        const int vr = (int)((long long)B - row0);
        for (int r = warp; r < vr; r += 8) {
            float2 pA = B1es[r][hp];
            float2 pB = B1es[r][hp + 1];
            float  a  = B0s[r][i0];
            float  dd = B0s[r][i3];
            float  m1 = s1 ? a : dd;
            float  m2 = s2 ? a : dd;
            float4 v;
            v.x = a  * pA.x;
            v.y = m1 * pA.y;
            v.z = m2 * pB.x;
            v.w = dd * pB.y;
            out4[r * 25 + lane] = v;
        }
    }
}

extern "C" void kernel_launch(void* const* d_in, const int* in_sizes, int n_in,
                              void* d_out, int out_size)
{
    const float* t     = (const float*)d_in[0];
    const float* knots = (const float*)d_in[1];
    float* out         = (float*)d_out;
    int B = in_sizes[0] / 2;                     // t is (B, 2)
    int grid = (B + ROWS - 1) / ROWS;
    bspline_outer_kernel<<<grid, THREADS>>>(t, knots, out, B);
}